// round 14
// baseline (speedup 1.0000x reference)
#include <cuda_runtime.h>
#include <cuda_bf16.h>
#include <cuda_fp16.h>

#define NB 8
#define NT 256
#define ND 256
#define NU 256

__device__ __half d_aeT_h[NB * NU * NT];  // aeT[b][u][e] fp16
__device__ float  d_ad   [NB * NT * NU];  // ad [b][t][u] fp32
__device__ float  d_alpha[NB * NT * NT];  // alpha[b][t][e] fp32

// ---------------------------------------------------------------------------
// tf32 MMA helpers
// ---------------------------------------------------------------------------
__device__ __forceinline__ unsigned f2tf(float x)
{
    unsigned r;
    asm("cvt.rna.tf32.f32 %0, %1;" : "=r"(r) : "f"(x));
    return r;
}

__device__ __forceinline__ void mma_tf32(float c[4], const unsigned a[4],
                                         unsigned b0, unsigned b1)
{
    asm volatile(
        "mma.sync.aligned.m16n8k8.row.col.f32.tf32.tf32.f32 "
        "{%0,%1,%2,%3}, {%4,%5,%6,%7}, {%8,%9}, {%0,%1,%2,%3};"
        : "+f"(c[0]), "+f"(c[1]), "+f"(c[2]), "+f"(c[3])
        : "r"(a[0]), "r"(a[1]), "r"(a[2]), "r"(a[3]), "r"(b0), "r"(b1));
}

__device__ __forceinline__ uint4 tf4(float4 v)
{
    return make_uint4(f2tf(v.x), f2tf(v.y), f2tf(v.z), f2tf(v.w));
}

// ---------------------------------------------------------------------------
// Front GEMM (tf32), 512 threads / 16 warps per CTA (warp grid 4x4, each warp
// 32x16). tf32 conversion at SMEM-store; inner loop pure LDS+MMA.
//   which=0: C[e][u] -> d_aeT_h[b][u][e] fp16 (transposed)
//   which=1: C[t][u] -> d_ad[b][t][u] fp32
// ---------------------------------------------------------------------------
__global__ __launch_bounds__(512) void gemm_kernel(const float* __restrict__ en,
                                                   const float* __restrict__ de,
                                                   const float* __restrict__ w_en,
                                                   const float* __restrict__ w_de)
{
    const int z     = blockIdx.z;
    const int b     = z >> 1;
    const int which = z & 1;

    const float* A  = which ? (de + b * NT * ND) : (en + b * NT * ND);
    const float* Bm = which ? w_de : w_en;

    const int m0 = blockIdx.y * 128;
    const int n0 = blockIdx.x * 64;

    __shared__ unsigned As[128][36];   // tf32 bits
    __shared__ unsigned Bs[32][68];    // tf32 bits

    const int tid  = threadIdx.x;
    const int w    = tid >> 5;       // 0..15
    const int lane = tid & 31;
    const int g    = lane >> 2;
    const int tig  = lane & 3;
    const int mw   = (w & 3) * 32;   // warp M offset
    const int nw   = (w >> 2) * 16;  // warp N offset

    float c[2][2][4];
#pragma unroll
    for (int mt = 0; mt < 2; mt++)
#pragma unroll
        for (int nt = 0; nt < 2; nt++)
#pragma unroll
            for (int i = 0; i < 4; i++) c[mt][nt][i] = 0.f;

    float4 pa[2], pb;
    const int ar[2] = {tid >> 3, (tid + 512) >> 3};
    const int ac    = (tid & 7) << 2;
    const int br    = tid >> 4;
    const int bc    = (tid & 15) << 2;

#pragma unroll
    for (int i = 0; i < 2; i++)
        pa[i] = *(const float4*)(A + (m0 + ar[i]) * 256 + 0 + ac);
    pb = *(const float4*)(Bm + (0 + br) * 256 + n0 + bc);

    for (int t = 0; t < 8; ++t) {
        __syncthreads();
#pragma unroll
        for (int i = 0; i < 2; i++)
            *(uint4*)&As[ar[i]][ac] = tf4(pa[i]);
        *(uint4*)&Bs[br][bc] = tf4(pb);
        __syncthreads();

        if (t < 7) {
            int k0 = (t + 1) * 32;
#pragma unroll
            for (int i = 0; i < 2; i++)
                pa[i] = *(const float4*)(A + (m0 + ar[i]) * 256 + k0 + ac);
            pb = *(const float4*)(Bm + (k0 + br) * 256 + n0 + bc);
        }

#pragma unroll
        for (int kt = 0; kt < 4; kt++) {
            unsigned a[2][4];
#pragma unroll
            for (int mt = 0; mt < 2; mt++) {
                int r = mw + mt * 16 + g;
                a[mt][0] = As[r][kt * 8 + tig];
                a[mt][1] = As[r + 8][kt * 8 + tig];
                a[mt][2] = As[r][kt * 8 + tig + 4];
                a[mt][3] = As[r + 8][kt * 8 + tig + 4];
            }
#pragma unroll
            for (int nt = 0; nt < 2; nt++) {
                unsigned b0 = Bs[kt * 8 + tig][nw + nt * 8 + g];
                unsigned b1 = Bs[kt * 8 + tig + 4][nw + nt * 8 + g];
                mma_tf32(c[0][nt], a[0], b0, b1);
                mma_tf32(c[1][nt], a[1], b0, b1);
            }
        }
    }

    if (which == 0) {
        __half* dst = d_aeT_h + b * NU * NT;
#pragma unroll
        for (int mt = 0; mt < 2; mt++)
#pragma unroll
            for (int nt = 0; nt < 2; nt++) {
                int e0 = m0 + mw + mt * 16 + g;
                int u0 = n0 + nw + nt * 8 + 2 * tig;
                dst[u0 * NT + e0]           = __float2half(c[mt][nt][0]);
                dst[(u0 + 1) * NT + e0]     = __float2half(c[mt][nt][1]);
                dst[u0 * NT + e0 + 8]       = __float2half(c[mt][nt][2]);
                dst[(u0 + 1) * NT + e0 + 8] = __float2half(c[mt][nt][3]);
            }
    } else {
        float* dst = d_ad + b * NT * NU;
#pragma unroll
        for (int mt = 0; mt < 2; mt++)
#pragma unroll
            for (int nt = 0; nt < 2; nt++) {
                int row = m0 + mw + mt * 16 + g;
                int col = n0 + nw + nt * 8 + 2 * tig;
                *(float2*)(dst + row * NU + col)       = make_float2(c[mt][nt][0], c[mt][nt][1]);
                *(float2*)(dst + (row + 8) * NU + col) = make_float2(c[mt][nt][2], c[mt][nt][3]);
            }
    }
}

// ---------------------------------------------------------------------------
// Context GEMM (tf32), 512 threads: out = de + alpha @ en.
// ---------------------------------------------------------------------------
__global__ __launch_bounds__(512) void ctx_kernel(const float* __restrict__ en,
                                                  const float* __restrict__ de,
                                                  float* __restrict__ out)
{
    const int b = blockIdx.z;
    const float* A  = d_alpha + b * NT * NT;
    const float* Bm = en + b * NT * ND;

    const int m0 = blockIdx.y * 128;
    const int n0 = blockIdx.x * 64;

    __shared__ unsigned As[128][36];
    __shared__ unsigned Bs[32][68];

    const int tid  = threadIdx.x;
    const int w    = tid >> 5;
    const int lane = tid & 31;
    const int g    = lane >> 2;
    const int tig  = lane & 3;
    const int mw   = (w & 3) * 32;
    const int nw   = (w >> 2) * 16;

    float c[2][2][4];
#pragma unroll
    for (int mt = 0; mt < 2; mt++)
#pragma unroll
        for (int nt = 0; nt < 2; nt++)
#pragma unroll
            for (int i = 0; i < 4; i++) c[mt][nt][i] = 0.f;

    float4 pa[2], pb;
    const int ar[2] = {tid >> 3, (tid + 512) >> 3};
    const int ac    = (tid & 7) << 2;
    const int br    = tid >> 4;
    const int bc    = (tid & 15) << 2;

#pragma unroll
    for (int i = 0; i < 2; i++)
        pa[i] = *(const float4*)(A + (m0 + ar[i]) * 256 + 0 + ac);
    pb = *(const float4*)(Bm + (0 + br) * 256 + n0 + bc);

    for (int t = 0; t < 8; ++t) {
        __syncthreads();
#pragma unroll
        for (int i = 0; i < 2; i++)
            *(uint4*)&As[ar[i]][ac] = tf4(pa[i]);
        *(uint4*)&Bs[br][bc] = tf4(pb);
        __syncthreads();

        if (t < 7) {
            int k0 = (t + 1) * 32;
#pragma unroll
            for (int i = 0; i < 2; i++)
                pa[i] = *(const float4*)(A + (m0 + ar[i]) * 256 + k0 + ac);
            pb = *(const float4*)(Bm + (k0 + br) * 256 + n0 + bc);
        }

#pragma unroll
        for (int kt = 0; kt < 4; kt++) {
            unsigned a[2][4];
#pragma unroll
            for (int mt = 0; mt < 2; mt++) {
                int r = mw + mt * 16 + g;
                a[mt][0] = As[r][kt * 8 + tig];
                a[mt][1] = As[r + 8][kt * 8 + tig];
                a[mt][2] = As[r][kt * 8 + tig + 4];
                a[mt][3] = As[r + 8][kt * 8 + tig + 4];
            }
#pragma unroll
            for (int nt = 0; nt < 2; nt++) {
                unsigned b0 = Bs[kt * 8 + tig][nw + nt * 8 + g];
                unsigned b1 = Bs[kt * 8 + tig + 4][nw + nt * 8 + g];
                mma_tf32(c[0][nt], a[0], b0, b1);
                mma_tf32(c[1][nt], a[1], b0, b1);
            }
        }
    }

    const float* deb = de + b * NT * ND;
    float* ob = out + b * NT * ND;
#pragma unroll
    for (int mt = 0; mt < 2; mt++)
#pragma unroll
        for (int nt = 0; nt < 2; nt++) {
            int row = m0 + mw + mt * 16 + g;
            int col = n0 + nw + nt * 8 + 2 * tig;
            float2 d0 = *(const float2*)(deb + row * ND + col);
            float2 d1 = *(const float2*)(deb + (row + 8) * ND + col);
            *(float2*)(ob + row * ND + col) =
                make_float2(c[mt][nt][0] + d0.x, c[mt][nt][1] + d0.y);
            *(float2*)(ob + (row + 8) * ND + col) =
                make_float2(c[mt][nt][2] + d1.x, c[mt][nt][3] + d1.y);
        }
}

// ---------------------------------------------------------------------------
// Attn kernel: scores + batched softmax -> alpha fp32.
// UT=64 staged tiles (half the barriers of UT=32); inside each tile the
// 19-MUFU/13-poly pattern runs twice with per-32-u fp16 flush (numerics
// identical to R13).
// ---------------------------------------------------------------------------
#define UT 64
#define TILE_HALFS (UT * 256)        // 16384 halfs = 32KB
#define NTILES (256 / UT)            // 4
#define NM 19

__device__ __forceinline__ void stage_tile(unsigned sbase, const __half* g, int tid)
{
    unsigned s = sbase + tid * 16;
    const char* gp = (const char*)g + tid * 16;
#pragma unroll
    for (int i = 0; i < 8; i++)
        asm volatile("cp.async.cg.shared.global [%0], [%1], 16;\n"
                     :: "r"(s + i * 4096), "l"(gp + i * 4096) : "memory");
    asm volatile("cp.async.commit_group;" ::: "memory");
}

struct PC { __half2 c0, c1, c2, c3, c4, c5, cl; };

__device__ __forceinline__ __half2 ptanh(__half2 x, const PC& P)
{
    __half2 xc = __hmax2(__hmin2(x, P.cl), __hneg2(P.cl));
    __half2 z  = __hmul2(xc, xc);
    __half2 h  = __hfma2(P.c5, z, P.c4);
    h = __hfma2(h, z, P.c3);
    h = __hfma2(h, z, P.c2);
    h = __hfma2(h, z, P.c1);
    h = __hfma2(h, z, P.c0);
    return __hmul2(xc, h);
}

__global__ __launch_bounds__(256) void attn_kernel(const float* __restrict__ nu)
{
    const int b   = blockIdx.x >> 6;
    const int t0  = (blockIdx.x & 63) << 2;
    const int tid = threadIdx.x;
    const int wid = tid >> 5;

    __shared__ __half buf[2][TILE_HALFS];   // 64KB double buffer
    __shared__ uint4  pk[256];
    __shared__ float4 redM[8];
    __shared__ float4 redS[8];

    const unsigned sb0 = (unsigned)__cvta_generic_to_shared(&buf[0][0]);
    const unsigned sb1 = (unsigned)__cvta_generic_to_shared(&buf[1][0]);
    const unsigned sbb[2] = {sb0, sb1};

    const __half* aeg = d_aeT_h + b * NU * NT;

    PC P;
    P.c0 = __float2half2_rn(0.992381f);
    P.c1 = __float2half2_rn(-0.282962f);
    P.c2 = __float2half2_rn(0.065192f);
    P.c3 = __float2half2_rn(-0.0087342f);
    P.c4 = __float2half2_rn(0.00059761f);
    P.c5 = __float2half2_rn(-1.6085e-5f);
    P.cl = __float2half2_rn(3.398f);

    stage_tile(sb0, aeg, tid);
    {
        const float* ap = d_ad + (b * NT + t0) * NU + tid;
        __half2 ad01 = __floats2half2_rn(ap[0],      ap[NU]);
        __half2 ad23 = __floats2half2_rn(ap[2 * NU], ap[3 * NU]);
        __half2 nu2  = __float2half2_rn(nu[tid]);
        uint4 p;
        p.x = *(unsigned*)&ad01;
        p.y = *(unsigned*)&ad23;
        p.z = *(unsigned*)&nu2;
        p.w = 0;
        pk[tid] = p;
    }

    float m0 = 0.f, m1 = 0.f, m2 = 0.f, m3 = 0.f;
    for (int t = 0; t < NTILES; ++t) {
        if (t < NTILES - 1)
            stage_tile(sbb[(t + 1) & 1], aeg + (t + 1) * TILE_HALFS, tid);
        if (t < NTILES - 1)
            asm volatile("cp.async.wait_group 1;" ::: "memory");
        else
            asm volatile("cp.async.wait_group 0;" ::: "memory");
        __syncthreads();

#pragma unroll
        for (int h = 0; h < 2; h++) {           // two 32-u halves per tile
            const __half* sa = &buf[t & 1][(h << 13) + tid];  // h*32*256
            const int u0 = t * UT + h * 32;

            __half2 am01 = __float2half2_rn(0.f);
            __half2 am23 = __float2half2_rn(0.f);
            __half2 ap01 = __float2half2_rn(0.f);
            __half2 ap23 = __float2half2_rn(0.f);

#pragma unroll
            for (int i = 0; i < NM; i++) {
                {
                    __half  a  = sa[i << 8];
                    uint4   p  = pk[u0 + i];
                    __half2 ah = __half2half2(a);
                    __half2 c01 = __hadd2(ah, *(__half2*)&p.x);
                    __half2 c23 = __hadd2(ah, *(__half2*)&p.y);
                    unsigned t01, t23;
                    asm("tanh.approx.f16x2 %0, %1;" : "=r"(t01) : "r"(*(unsigned*)&c01));
                    asm("tanh.approx.f16x2 %0, %1;" : "=r"(t23) : "r"(*(unsigned*)&c23));
                    am01 = __hfma2(*(__half2*)&t01, *(__half2*)&p.z, am01);
                    am23 = __hfma2(*(__half2*)&t23, *(__half2*)&p.z, am23);
                }
                if (i < 32 - NM) {
                    int k = NM + i;
                    __half  a  = sa[k << 8];
                    uint4   p  = pk[u0 + k];
                    __half2 ah = __half2half2(a);
                    __half2 c01 = __hadd2(ah, *(__half2*)&p.x);
                    __half2 c23 = __hadd2(ah, *(__half2*)&p.y);
                    __half2 t01 = ptanh(c01, P);
                    __half2 t23 = ptanh(c23, P);
                    ap01 = __hfma2(t01, *(__half2*)&p.z, ap01);
                    ap23 = __hfma2(t23, *(__half2*)&p.z, ap23);
                }
            }
            float2 f01 = __half22float2(am01);
            float2 f23 = __half22float2(am23);
            float2 g01 = __half22float2(ap01);
            float2 g23 = __half22float2(ap23);
            m0 += f01.x + g01.x; m1 += f01.y + g01.y;
            m2 += f23.x + g23.x; m3 += f23.y + g23.y;
        }
        __syncthreads();
    }

    // ---- batched softmax over e (all 4 rows, 2 barriers) ----
    float4 mu = make_float4(m0, m1, m2, m3);
    float4 mx = mu;
#pragma unroll
    for (int o = 16; o; o >>= 1) {
        mx.x = fmaxf(mx.x, __shfl_xor_sync(0xffffffffu, mx.x, o));
        mx.y = fmaxf(mx.y, __shfl_xor_sync(0xffffffffu, mx.y, o));
        mx.z = fmaxf(mx.z, __shfl_xor_sync(0xffffffffu, mx.z, o));
        mx.w = fmaxf(mx.w, __shfl_xor_sync(0xffffffffu, mx.w, o));
    }
    if ((tid & 31) == 0) redM[wid] = mx;
    __syncthreads();
    mx = redM[0];
#pragma unroll
    for (int i = 1; i < 8; i++) {
        float4 r = redM[i];
        mx.x = fmaxf(mx.x, r.x); mx.y = fmaxf(mx.y, r.y);
        mx.z = fmaxf(mx.z, r.z); mx.w = fmaxf(mx.w, r.w);
    }
    float4 ex = make_float4(__expf(mu.x - mx.x), __expf(mu.y - mx.y),
                            __expf(mu.z - mx.z), __expf(mu.w - mx.w));
    float4 s = ex;
#pragma unroll
    for (int o = 16; o; o >>= 1) {
        s.x += __shfl_xor_sync(0xffffffffu, s.x, o);
        s.y += __shfl_xor_sync(0xffffffffu, s.y, o);
        s.z += __shfl_xor_sync(0xffffffffu, s.z, o);
        s.w += __shfl_xor_sync(0xffffffffu, s.w, o);
    }
    if ((tid & 31) == 0) redS[wid] = s;
    __syncthreads();
    s = redS[0];
#pragma unroll
    for (int i = 1; i < 8; i++) {
        float4 r = redS[i];
        s.x += r.x; s.y += r.y; s.z += r.z; s.w += r.w;
    }

    float* ap = d_alpha + (b * NT + t0) * NT + tid;
    ap[0]      = __fdividef(ex.x, s.x);
    ap[NT]     = __fdividef(ex.y, s.y);
    ap[2 * NT] = __fdividef(ex.z, s.z);
    ap[3 * NT] = __fdividef(ex.w, s.w);
}

extern "C" void kernel_launch(void* const* d_in, const int* in_sizes, int n_in,
                              void* d_out, int out_size)
{
    const float* en   = (const float*)d_in[0];
    const float* de   = (const float*)d_in[1];
    const float* w_en = (const float*)d_in[2];
    const float* w_de = (const float*)d_in[3];
    const float* nu   = (const float*)d_in[4];
    float* out = (float*)d_out;

    dim3 gg(4, 2, 16);
    gemm_kernel<<<gg, 512>>>(en, de, w_en, w_de);
    attn_kernel<<<NB * (NT / 4), 256>>>(nu);
    dim3 gc(4, 2, 8);
    ctx_kernel<<<gc, 512>>>(en, de, out);
}

// round 15
// speedup vs baseline: 1.0084x; 1.0084x over previous
#include <cuda_runtime.h>
#include <cuda_bf16.h>
#include <cuda_fp16.h>

#define NB 8
#define NT 256
#define ND 256
#define NU 256

__device__ __half d_aeT_h[NB * NU * NT];  // aeT[b][u][e] fp16
__device__ float  d_ad   [NB * NT * NU];  // ad [b][t][u] fp32
__device__ float  d_alpha[NB * NT * NT];  // alpha[b][t][e] fp32

// ---------------------------------------------------------------------------
// tf32 MMA helpers
// ---------------------------------------------------------------------------
__device__ __forceinline__ unsigned f2tf(float x)
{
    unsigned r;
    asm("cvt.rna.tf32.f32 %0, %1;" : "=r"(r) : "f"(x));
    return r;
}

__device__ __forceinline__ void mma_tf32(float c[4], const unsigned a[4],
                                         unsigned b0, unsigned b1)
{
    asm volatile(
        "mma.sync.aligned.m16n8k8.row.col.f32.tf32.tf32.f32 "
        "{%0,%1,%2,%3}, {%4,%5,%6,%7}, {%8,%9}, {%0,%1,%2,%3};"
        : "+f"(c[0]), "+f"(c[1]), "+f"(c[2]), "+f"(c[3])
        : "r"(a[0]), "r"(a[1]), "r"(a[2]), "r"(a[3]), "r"(b0), "r"(b1));
}

__device__ __forceinline__ void cp16(unsigned dst, const void* src)
{
    asm volatile("cp.async.cg.shared.global [%0], [%1], 16;\n"
                 :: "r"(dst), "l"(src) : "memory");
}

// ---------------------------------------------------------------------------
// Pipelined tf32 GEMM core: tile 128(M)x64(N), K-chunk 16, 4-stage cp.async.
// Stage layout (12KB): A 128x16 fp32 (8KB, 64B rows, swizzle chunk^((r>>1)&3)),
//                      B 16x64 fp32 (4KB, 256B rows, swizzle chunk^((row&3)<<1)).
// One __syncthreads per chunk; LDG latency hidden by 3-chunk pipeline depth.
// ---------------------------------------------------------------------------
#define STG_BYTES 12288
#define B_OFF     8192

__device__ __forceinline__ void stage_chunk(unsigned sbase, const float* A,
                                            const float* Bm, int m0, int n0,
                                            int k0, int tid)
{
#pragma unroll
    for (int i = 0; i < 2; i++) {          // A: 512 16B-chunks / 256 threads
        int q   = tid * 2 + i;
        int row = q >> 2, cc = q & 3;
        unsigned dst = sbase + row * 64 + ((cc ^ ((row >> 1) & 3)) << 4);
        cp16(dst, A + (m0 + row) * 256 + k0 + cc * 4);
    }
    {                                      // B: 256 chunks / 256 threads
        int row = tid >> 4, cc = tid & 15;
        unsigned dst = sbase + B_OFF + row * 256 + ((cc ^ ((row & 3) << 1)) << 4);
        cp16(dst, Bm + (k0 + row) * 256 + n0 + cc * 4);
    }
    asm volatile("cp.async.commit_group;" ::: "memory");
}

// compute one 16-k chunk from SMEM slot; accumulators c[2][4][4]
__device__ __forceinline__ void compute_chunk(const char* sA, const char* sB,
                                              int mw, int nw, int g, int tig,
                                              float c[2][4][4])
{
#pragma unroll
    for (int kt = 0; kt < 2; kt++) {
        unsigned a[2][4];
#pragma unroll
        for (int mt = 0; mt < 2; mt++) {
            int r1 = mw + mt * 16 + g;
            int r2 = r1 + 8;
            int sw1 = (kt * 2)     ^ ((r1 >> 1) & 3);
            int sw2 = (kt * 2 + 1) ^ ((r1 >> 1) & 3);   // (r2>>1)&3 == (r1>>1)&3
            a[mt][0] = f2tf(*(const float*)(sA + r1 * 64 + sw1 * 16 + tig * 4));
            a[mt][1] = f2tf(*(const float*)(sA + r2 * 64 + sw1 * 16 + tig * 4));
            a[mt][2] = f2tf(*(const float*)(sA + r1 * 64 + sw2 * 16 + tig * 4));
            a[mt][3] = f2tf(*(const float*)(sA + r2 * 64 + sw2 * 16 + tig * 4));
        }
        int rb1 = kt * 8 + tig;
        int rb2 = rb1 + 4;
#pragma unroll
        for (int nt = 0; nt < 4; nt++) {
            int cb = nw + nt * 8 + g;
            int sw = (cb >> 2) ^ (tig << 1);            // rb&3 == tig for both rows
            unsigned b0 = f2tf(*(const float*)(sB + rb1 * 256 + sw * 16 + (cb & 3) * 4));
            unsigned b1 = f2tf(*(const float*)(sB + rb2 * 256 + sw * 16 + (cb & 3) * 4));
            mma_tf32(c[0][nt], a[0], b0, b1);
            mma_tf32(c[1][nt], a[1], b0, b1);
        }
    }
}

#define PIPE_LOOP(Aptr, Bptr)                                                  \
    stage_chunk(smbase + 0 * STG_BYTES, Aptr, Bptr, m0, n0, 0,  tid);          \
    stage_chunk(smbase + 1 * STG_BYTES, Aptr, Bptr, m0, n0, 16, tid);          \
    stage_chunk(smbase + 2 * STG_BYTES, Aptr, Bptr, m0, n0, 32, tid);          \
    for (int t = 0; t < 16; ++t) {                                             \
        if (t < 14)      asm volatile("cp.async.wait_group 2;" ::: "memory");  \
        else if (t == 14) asm volatile("cp.async.wait_group 1;" ::: "memory"); \
        else             asm volatile("cp.async.wait_group 0;" ::: "memory");  \
        __syncthreads();                                                       \
        if (t + 3 < 16)                                                        \
            stage_chunk(smbase + ((t + 3) & 3) * STG_BYTES, Aptr, Bptr,        \
                        m0, n0, (t + 3) * 16, tid);                            \
        const char* sA = smem + ((t & 3) * STG_BYTES);                         \
        const char* sB = sA + B_OFF;                                           \
        compute_chunk(sA, sB, mw, nw, g, tig, c);                              \
    }

// ---------------------------------------------------------------------------
// Front GEMM: which=0 -> d_aeT_h[b][u][e] fp16 (transposed); which=1 -> d_ad.
// ---------------------------------------------------------------------------
__global__ __launch_bounds__(256) void gemm_kernel(const float* __restrict__ en,
                                                   const float* __restrict__ de,
                                                   const float* __restrict__ w_en,
                                                   const float* __restrict__ w_de)
{
    const int z     = blockIdx.z;
    const int b     = z >> 1;
    const int which = z & 1;

    const float* A  = which ? (de + b * NT * ND) : (en + b * NT * ND);
    const float* Bm = which ? w_de : w_en;

    const int m0 = blockIdx.y * 128;
    const int n0 = blockIdx.x * 64;

    __shared__ char smem[4 * STG_BYTES];   // 48KB
    const unsigned smbase = (unsigned)__cvta_generic_to_shared(smem);

    const int tid  = threadIdx.x;
    const int w    = tid >> 5;
    const int lane = tid & 31;
    const int g    = lane >> 2;
    const int tig  = lane & 3;
    const int mw   = (w & 3) * 32;
    const int nw   = (w >> 2) * 32;

    float c[2][4][4];
#pragma unroll
    for (int mt = 0; mt < 2; mt++)
#pragma unroll
        for (int nt = 0; nt < 4; nt++)
#pragma unroll
            for (int i = 0; i < 4; i++) c[mt][nt][i] = 0.f;

    PIPE_LOOP(A, Bm)

    if (which == 0) {
        __half* dst = d_aeT_h + b * NU * NT;
#pragma unroll
        for (int mt = 0; mt < 2; mt++)
#pragma unroll
            for (int nt = 0; nt < 4; nt++) {
                int e0 = m0 + mw + mt * 16 + g;
                int u0 = n0 + nw + nt * 8 + 2 * tig;
                dst[u0 * NT + e0]           = __float2half(c[mt][nt][0]);
                dst[(u0 + 1) * NT + e0]     = __float2half(c[mt][nt][1]);
                dst[u0 * NT + e0 + 8]       = __float2half(c[mt][nt][2]);
                dst[(u0 + 1) * NT + e0 + 8] = __float2half(c[mt][nt][3]);
            }
    } else {
        float* dst = d_ad + b * NT * NU;
#pragma unroll
        for (int mt = 0; mt < 2; mt++)
#pragma unroll
            for (int nt = 0; nt < 4; nt++) {
                int row = m0 + mw + mt * 16 + g;
                int col = n0 + nw + nt * 8 + 2 * tig;
                *(float2*)(dst + row * NU + col)       = make_float2(c[mt][nt][0], c[mt][nt][1]);
                *(float2*)(dst + (row + 8) * NU + col) = make_float2(c[mt][nt][2], c[mt][nt][3]);
            }
    }
}

// ---------------------------------------------------------------------------
// Context GEMM: out = de + alpha @ en (same pipeline).
// ---------------------------------------------------------------------------
__global__ __launch_bounds__(256) void ctx_kernel(const float* __restrict__ en,
                                                  const float* __restrict__ de,
                                                  float* __restrict__ out)
{
    const int b = blockIdx.z;
    const float* A  = d_alpha + b * NT * NT;
    const float* Bm = en + b * NT * ND;

    const int m0 = blockIdx.y * 128;
    const int n0 = blockIdx.x * 64;

    __shared__ char smem[4 * STG_BYTES];
    const unsigned smbase = (unsigned)__cvta_generic_to_shared(smem);

    const int tid  = threadIdx.x;
    const int w    = tid >> 5;
    const int lane = tid & 31;
    const int g    = lane >> 2;
    const int tig  = lane & 3;
    const int mw   = (w & 3) * 32;
    const int nw   = (w >> 2) * 32;

    float c[2][4][4];
#pragma unroll
    for (int mt = 0; mt < 2; mt++)
#pragma unroll
        for (int nt = 0; nt < 4; nt++)
#pragma unroll
            for (int i = 0; i < 4; i++) c[mt][nt][i] = 0.f;

    PIPE_LOOP(A, Bm)

    const float* deb = de + b * NT * ND;
    float* ob = out + b * NT * ND;
#pragma unroll
    for (int mt = 0; mt < 2; mt++)
#pragma unroll
        for (int nt = 0; nt < 4; nt++) {
            int row = m0 + mw + mt * 16 + g;
            int col = n0 + nw + nt * 8 + 2 * tig;
            float2 d0 = *(const float2*)(deb + row * ND + col);
            float2 d1 = *(const float2*)(deb + (row + 8) * ND + col);
            *(float2*)(ob + row * ND + col) =
                make_float2(c[mt][nt][0] + d0.x, c[mt][nt][1] + d0.y);
            *(float2*)(ob + (row + 8) * ND + col) =
                make_float2(c[mt][nt][2] + d1.x, c[mt][nt][3] + d1.y);
        }
}

// ---------------------------------------------------------------------------
// Attn kernel (unchanged from R14): scores (19 MUFU + 13 poly per 32 u,
// UT=64 staged tiles) + batched softmax -> alpha fp32.
// ---------------------------------------------------------------------------
#define UT 64
#define TILE_HALFS (UT * 256)
#define NTILES (256 / UT)
#define NM 19

__device__ __forceinline__ void stage_tile(unsigned sbase, const __half* g, int tid)
{
    unsigned s = sbase + tid * 16;
    const char* gp = (const char*)g + tid * 16;
#pragma unroll
    for (int i = 0; i < 8; i++)
        asm volatile("cp.async.cg.shared.global [%0], [%1], 16;\n"
                     :: "r"(s + i * 4096), "l"(gp + i * 4096) : "memory");
    asm volatile("cp.async.commit_group;" ::: "memory");
}

struct PC { __half2 c0, c1, c2, c3, c4, c5, cl; };

__device__ __forceinline__ __half2 ptanh(__half2 x, const PC& P)
{
    __half2 xc = __hmax2(__hmin2(x, P.cl), __hneg2(P.cl));
    __half2 z  = __hmul2(xc, xc);
    __half2 h  = __hfma2(P.c5, z, P.c4);
    h = __hfma2(h, z, P.c3);
    h = __hfma2(h, z, P.c2);
    h = __hfma2(h, z, P.c1);
    h = __hfma2(h, z, P.c0);
    return __hmul2(xc, h);
}

__global__ __launch_bounds__(256) void attn_kernel(const float* __restrict__ nu)
{
    const int b   = blockIdx.x >> 6;
    const int t0  = (blockIdx.x & 63) << 2;
    const int tid = threadIdx.x;
    const int wid = tid >> 5;

    __shared__ __half buf[2][TILE_HALFS];   // 64KB double buffer
    __shared__ uint4  pk[256];
    __shared__ float4 redM[8];
    __shared__ float4 redS[8];

    const unsigned sb0 = (unsigned)__cvta_generic_to_shared(&buf[0][0]);
    const unsigned sb1 = (unsigned)__cvta_generic_to_shared(&buf[1][0]);
    const unsigned sbb[2] = {sb0, sb1};

    const __half* aeg = d_aeT_h + b * NU * NT;

    PC P;
    P.c0 = __float2half2_rn(0.992381f);
    P.c1 = __float2half2_rn(-0.282962f);
    P.c2 = __float2half2_rn(0.065192f);
    P.c3 = __float2half2_rn(-0.0087342f);
    P.c4 = __float2half2_rn(0.00059761f);
    P.c5 = __float2half2_rn(-1.6085e-5f);
    P.cl = __float2half2_rn(3.398f);

    stage_tile(sb0, aeg, tid);
    {
        const float* ap = d_ad + (b * NT + t0) * NU + tid;
        __half2 ad01 = __floats2half2_rn(ap[0],      ap[NU]);
        __half2 ad23 = __floats2half2_rn(ap[2 * NU], ap[3 * NU]);
        __half2 nu2  = __float2half2_rn(nu[tid]);
        uint4 p;
        p.x = *(unsigned*)&ad01;
        p.y = *(unsigned*)&ad23;
        p.z = *(unsigned*)&nu2;
        p.w = 0;
        pk[tid] = p;
    }

    float m0 = 0.f, m1 = 0.f, m2 = 0.f, m3 = 0.f;
    for (int t = 0; t < NTILES; ++t) {
        if (t < NTILES - 1)
            stage_tile(sbb[(t + 1) & 1], aeg + (t + 1) * TILE_HALFS, tid);
        if (t < NTILES - 1)
            asm volatile("cp.async.wait_group 1;" ::: "memory");
        else
            asm volatile("cp.async.wait_group 0;" ::: "memory");
        __syncthreads();

#pragma unroll
        for (int h = 0; h < 2; h++) {
            const __half* sa = &buf[t & 1][(h << 13) + tid];
            const int u0 = t * UT + h * 32;

            __half2 am01 = __float2half2_rn(0.f);
            __half2 am23 = __float2half2_rn(0.f);
            __half2 ap01 = __float2half2_rn(0.f);
            __half2 ap23 = __float2half2_rn(0.f);

#pragma unroll
            for (int i = 0; i < NM; i++) {
                {
                    __half  a  = sa[i << 8];
                    uint4   p  = pk[u0 + i];
                    __half2 ah = __half2half2(a);
                    __half2 c01 = __hadd2(ah, *(__half2*)&p.x);
                    __half2 c23 = __hadd2(ah, *(__half2*)&p.y);
                    unsigned t01, t23;
                    asm("tanh.approx.f16x2 %0, %1;" : "=r"(t01) : "r"(*(unsigned*)&c01));
                    asm("tanh.approx.f16x2 %0, %1;" : "=r"(t23) : "r"(*(unsigned*)&c23));
                    am01 = __hfma2(*(__half2*)&t01, *(__half2*)&p.z, am01);
                    am23 = __hfma2(*(__half2*)&t23, *(__half2*)&p.z, am23);
                }
                if (i < 32 - NM) {
                    int k = NM + i;
                    __half  a  = sa[k << 8];
                    uint4   p  = pk[u0 + k];
                    __half2 ah = __half2half2(a);
                    __half2 c01 = __hadd2(ah, *(__half2*)&p.x);
                    __half2 c23 = __hadd2(ah, *(__half2*)&p.y);
                    __half2 t01 = ptanh(c01, P);
                    __half2 t23 = ptanh(c23, P);
                    ap01 = __hfma2(t01, *(__half2*)&p.z, ap01);
                    ap23 = __hfma2(t23, *(__half2*)&p.z, ap23);
                }
            }
            float2 f01 = __half22float2(am01);
            float2 f23 = __half22float2(am23);
            float2 g01 = __half22float2(ap01);
            float2 g23 = __half22float2(ap23);
            m0 += f01.x + g01.x; m1 += f01.y + g01.y;
            m2 += f23.x + g23.x; m3 += f23.y + g23.y;
        }
        __syncthreads();
    }

    float4 mu = make_float4(m0, m1, m2, m3);
    float4 mx = mu;
#pragma unroll
    for (int o = 16; o; o >>= 1) {
        mx.x = fmaxf(mx.x, __shfl_xor_sync(0xffffffffu, mx.x, o));
        mx.y = fmaxf(mx.y, __shfl_xor_sync(0xffffffffu, mx.y, o));
        mx.z = fmaxf(mx.z, __shfl_xor_sync(0xffffffffu, mx.z, o));
        mx.w = fmaxf(mx.w, __shfl_xor_sync(0xffffffffu, mx.w, o));
    }
    if ((tid & 31) == 0) redM[wid] = mx;
    __syncthreads();
    mx = redM[0];
#pragma unroll
    for (int i = 1; i < 8; i++) {
        float4 r = redM[i];
        mx.x = fmaxf(mx.x, r.x); mx.y = fmaxf(mx.y, r.y);
        mx.z = fmaxf(mx.z, r.z); mx.w = fmaxf(mx.w, r.w);
    }
    float4 ex = make_float4(__expf(mu.x - mx.x), __expf(mu.y - mx.y),
                            __expf(mu.z - mx.z), __expf(mu.w - mx.w));
    float4 s = ex;
#pragma unroll
    for (int o = 16; o; o >>= 1) {
        s.x += __shfl_xor_sync(0xffffffffu, s.x, o);
        s.y += __shfl_xor_sync(0xffffffffu, s.y, o);
        s.z += __shfl_xor_sync(0xffffffffu, s.z, o);
        s.w += __shfl_xor_sync(0xffffffffu, s.w, o);
    }
    if ((tid & 31) == 0) redS[wid] = s;
    __syncthreads();
    s = redS[0];
#pragma unroll
    for (int i = 1; i < 8; i++) {
        float4 r = redS[i];
        s.x += r.x; s.y += r.y; s.z += r.z; s.w += r.w;
    }

    float* ap = d_alpha + (b * NT + t0) * NT + tid;
    ap[0]      = __fdividef(ex.x, s.x);
    ap[NT]     = __fdividef(ex.y, s.y);
    ap[2 * NT] = __fdividef(ex.z, s.z);
    ap[3 * NT] = __fdividef(ex.w, s.w);
}

extern "C" void kernel_launch(void* const* d_in, const int* in_sizes, int n_in,
                              void* d_out, int out_size)
{
    const float* en   = (const float*)d_in[0];
    const float* de   = (const float*)d_in[1];
    const float* w_en = (const float*)d_in[2];
    const float* w_de = (const float*)d_in[3];
    const float* nu   = (const float*)d_in[4];
    float* out = (float*)d_out;

    dim3 gg(4, 2, 16);
    gemm_kernel<<<gg, 256>>>(en, de, w_en, w_de);
    attn_kernel<<<NB * (NT / 4), 256>>>(nu);
    dim3 gc(4, 2, 8);
    ctx_kernel<<<gc, 256>>>(en, de, out);
}

// round 16
// speedup vs baseline: 1.0770x; 1.0680x over previous
#include <cuda_runtime.h>
#include <cuda_bf16.h>
#include <cuda_fp16.h>

#define NB 8
#define NT 256
#define ND 256
#define NU 256

__device__ __half d_aeT_h[NB * NU * NT];  // aeT[b][u][e] fp16
__device__ float  d_ad   [NB * NT * NU];  // ad [b][t][u] fp32
__device__ float  d_alpha[NB * NT * NT];  // alpha[b][t][e] fp32

// ---------------------------------------------------------------------------
// tf32 MMA helpers
// ---------------------------------------------------------------------------
__device__ __forceinline__ unsigned f2tf(float x)
{
    unsigned r;
    asm("cvt.rna.tf32.f32 %0, %1;" : "=r"(r) : "f"(x));
    return r;
}

__device__ __forceinline__ void mma_tf32(float c[4], const unsigned a[4],
                                         unsigned b0, unsigned b1)
{
    asm volatile(
        "mma.sync.aligned.m16n8k8.row.col.f32.tf32.tf32.f32 "
        "{%0,%1,%2,%3}, {%4,%5,%6,%7}, {%8,%9}, {%0,%1,%2,%3};"
        : "+f"(c[0]), "+f"(c[1]), "+f"(c[2]), "+f"(c[3])
        : "r"(a[0]), "r"(a[1]), "r"(a[2]), "r"(a[3]), "r"(b0), "r"(b1));
}

__device__ __forceinline__ uint4 tf4(float4 v)
{
    return make_uint4(f2tf(v.x), f2tf(v.y), f2tf(v.z), f2tf(v.w));
}

// ---------------------------------------------------------------------------
// 64x64-tile tf32 GEMM body (K-chunk 32, store-time cvt, reg prefetch).
// 256 threads = 8 warps in a 2(M)x4(N) grid; each warp 32x16, c[2][2][4].
// Grid has 2x the CTAs of the 128x64 version -> 2 independent CTAs/SM.
// ---------------------------------------------------------------------------
#define GEMM_BODY(Aptr, Bptr)                                                  \
    float4 pa[2], pb[2];                                                       \
    const int ar[2] = {tid >> 3, (tid + 256) >> 3};                            \
    const int ac    = (tid & 7) << 2;                                          \
    const int br[2] = {tid >> 4, (tid + 256) >> 4};                            \
    const int bc    = (tid & 15) << 2;                                         \
    for (int i = 0; i < 2; i++)                                                \
        pa[i] = *(const float4*)(Aptr + (m0 + ar[i]) * 256 + 0 + ac);          \
    for (int i = 0; i < 2; i++)                                                \
        pb[i] = *(const float4*)(Bptr + (0 + br[i]) * 256 + n0 + bc);          \
    for (int t = 0; t < 8; ++t) {                                              \
        __syncthreads();                                                       \
        for (int i = 0; i < 2; i++)                                            \
            *(uint4*)&As[ar[i]][ac] = tf4(pa[i]);                              \
        for (int i = 0; i < 2; i++)                                            \
            *(uint4*)&Bs[br[i]][bc] = tf4(pb[i]);                              \
        __syncthreads();                                                       \
        if (t < 7) {                                                           \
            int k0 = (t + 1) * 32;                                             \
            for (int i = 0; i < 2; i++)                                        \
                pa[i] = *(const float4*)(Aptr + (m0 + ar[i]) * 256 + k0 + ac); \
            for (int i = 0; i < 2; i++)                                        \
                pb[i] = *(const float4*)(Bptr + (k0 + br[i]) * 256 + n0 + bc); \
        }                                                                      \
        _Pragma("unroll")                                                      \
        for (int kt = 0; kt < 4; kt++) {                                       \
            unsigned a[2][4];                                                  \
            _Pragma("unroll")                                                  \
            for (int mt = 0; mt < 2; mt++) {                                   \
                int r = mw + mt * 16 + g;                                      \
                a[mt][0] = As[r][kt * 8 + tig];                                \
                a[mt][1] = As[r + 8][kt * 8 + tig];                            \
                a[mt][2] = As[r][kt * 8 + tig + 4];                            \
                a[mt][3] = As[r + 8][kt * 8 + tig + 4];                        \
            }                                                                  \
            _Pragma("unroll")                                                  \
            for (int nt = 0; nt < 2; nt++) {                                   \
                unsigned b0 = Bs[kt * 8 + tig][nw + nt * 8 + g];               \
                unsigned b1 = Bs[kt * 8 + tig + 4][nw + nt * 8 + g];           \
                mma_tf32(c[0][nt], a[0], b0, b1);                              \
                mma_tf32(c[1][nt], a[1], b0, b1);                              \
            }                                                                  \
        }                                                                      \
    }

// ---------------------------------------------------------------------------
// Front GEMM: which=0 -> d_aeT_h[b][u][e] fp16 (transposed); which=1 -> d_ad.
// Grid (4 n, 4 m, 16 bz) = 256 CTAs.
// ---------------------------------------------------------------------------
__global__ __launch_bounds__(256) void gemm_kernel(const float* __restrict__ en,
                                                   const float* __restrict__ de,
                                                   const float* __restrict__ w_en,
                                                   const float* __restrict__ w_de)
{
    const int z     = blockIdx.z;
    const int b     = z >> 1;
    const int which = z & 1;

    const float* A  = which ? (de + b * NT * ND) : (en + b * NT * ND);
    const float* Bm = which ? w_de : w_en;

    const int m0 = blockIdx.y * 64;
    const int n0 = blockIdx.x * 64;

    __shared__ unsigned As[64][36];   // tf32 bits, m x k
    __shared__ unsigned Bs[32][68];   // tf32 bits, k x n

    const int tid  = threadIdx.x;
    const int w    = tid >> 5;
    const int lane = tid & 31;
    const int g    = lane >> 2;
    const int tig  = lane & 3;
    const int mw   = (w & 1) * 32;    // 2 warp-rows
    const int nw   = (w >> 1) * 16;   // 4 warp-cols

    float c[2][2][4];
#pragma unroll
    for (int mt = 0; mt < 2; mt++)
#pragma unroll
        for (int nt = 0; nt < 2; nt++)
#pragma unroll
            for (int i = 0; i < 4; i++) c[mt][nt][i] = 0.f;

    GEMM_BODY(A, Bm)

    if (which == 0) {
        __half* dst = d_aeT_h + b * NU * NT;
#pragma unroll
        for (int mt = 0; mt < 2; mt++)
#pragma unroll
            for (int nt = 0; nt < 2; nt++) {
                int e0 = m0 + mw + mt * 16 + g;
                int u0 = n0 + nw + nt * 8 + 2 * tig;
                dst[u0 * NT + e0]           = __float2half(c[mt][nt][0]);
                dst[(u0 + 1) * NT + e0]     = __float2half(c[mt][nt][1]);
                dst[u0 * NT + e0 + 8]       = __float2half(c[mt][nt][2]);
                dst[(u0 + 1) * NT + e0 + 8] = __float2half(c[mt][nt][3]);
            }
    } else {
        float* dst = d_ad + b * NT * NU;
#pragma unroll
        for (int mt = 0; mt < 2; mt++)
#pragma unroll
            for (int nt = 0; nt < 2; nt++) {
                int row = m0 + mw + mt * 16 + g;
                int col = n0 + nw + nt * 8 + 2 * tig;
                *(float2*)(dst + row * NU + col)       = make_float2(c[mt][nt][0], c[mt][nt][1]);
                *(float2*)(dst + (row + 8) * NU + col) = make_float2(c[mt][nt][2], c[mt][nt][3]);
            }
    }
}

// ---------------------------------------------------------------------------
// Context GEMM: out = de + alpha @ en. Grid (4, 4, 8) = 128 CTAs.
// ---------------------------------------------------------------------------
__global__ __launch_bounds__(256) void ctx_kernel(const float* __restrict__ en,
                                                  const float* __restrict__ de,
                                                  float* __restrict__ out)
{
    const int b = blockIdx.z;
    const float* A  = d_alpha + b * NT * NT;
    const float* Bm = en + b * NT * ND;

    const int m0 = blockIdx.y * 64;
    const int n0 = blockIdx.x * 64;

    __shared__ unsigned As[64][36];
    __shared__ unsigned Bs[32][68];

    const int tid  = threadIdx.x;
    const int w    = tid >> 5;
    const int lane = tid & 31;
    const int g    = lane >> 2;
    const int tig  = lane & 3;
    const int mw   = (w & 1) * 32;
    const int nw   = (w >> 1) * 16;

    float c[2][2][4];
#pragma unroll
    for (int mt = 0; mt < 2; mt++)
#pragma unroll
        for (int nt = 0; nt < 2; nt++)
#pragma unroll
            for (int i = 0; i < 4; i++) c[mt][nt][i] = 0.f;

    GEMM_BODY(A, Bm)

    const float* deb = de + b * NT * ND;
    float* ob = out + b * NT * ND;
#pragma unroll
    for (int mt = 0; mt < 2; mt++)
#pragma unroll
        for (int nt = 0; nt < 2; nt++) {
            int row = m0 + mw + mt * 16 + g;
            int col = n0 + nw + nt * 8 + 2 * tig;
            float2 d0 = *(const float2*)(deb + row * ND + col);
            float2 d1 = *(const float2*)(deb + (row + 8) * ND + col);
            *(float2*)(ob + row * ND + col) =
                make_float2(c[mt][nt][0] + d0.x, c[mt][nt][1] + d0.y);
            *(float2*)(ob + (row + 8) * ND + col) =
                make_float2(c[mt][nt][2] + d1.x, c[mt][nt][3] + d1.y);
        }
}

// ---------------------------------------------------------------------------
// Attn kernel (unchanged from R14): scores (19 MUFU + 13 poly per 32 u,
// UT=64 staged tiles) + batched softmax -> alpha fp32.
// ---------------------------------------------------------------------------
#define UT 64
#define TILE_HALFS (UT * 256)
#define NTILES (256 / UT)
#define NM 19

__device__ __forceinline__ void stage_tile(unsigned sbase, const __half* g, int tid)
{
    unsigned s = sbase + tid * 16;
    const char* gp = (const char*)g + tid * 16;
#pragma unroll
    for (int i = 0; i < 8; i++)
        asm volatile("cp.async.cg.shared.global [%0], [%1], 16;\n"
                     :: "r"(s + i * 4096), "l"(gp + i * 4096) : "memory");
    asm volatile("cp.async.commit_group;" ::: "memory");
}

struct PC { __half2 c0, c1, c2, c3, c4, c5, cl; };

__device__ __forceinline__ __half2 ptanh(__half2 x, const PC& P)
{
    __half2 xc = __hmax2(__hmin2(x, P.cl), __hneg2(P.cl));
    __half2 z  = __hmul2(xc, xc);
    __half2 h  = __hfma2(P.c5, z, P.c4);
    h = __hfma2(h, z, P.c3);
    h = __hfma2(h, z, P.c2);
    h = __hfma2(h, z, P.c1);
    h = __hfma2(h, z, P.c0);
    return __hmul2(xc, h);
}

__global__ __launch_bounds__(256) void attn_kernel(const float* __restrict__ nu)
{
    const int b   = blockIdx.x >> 6;
    const int t0  = (blockIdx.x & 63) << 2;
    const int tid = threadIdx.x;
    const int wid = tid >> 5;

    __shared__ __half buf[2][TILE_HALFS];   // 64KB double buffer
    __shared__ uint4  pk[256];
    __shared__ float4 redM[8];
    __shared__ float4 redS[8];

    const unsigned sb0 = (unsigned)__cvta_generic_to_shared(&buf[0][0]);
    const unsigned sb1 = (unsigned)__cvta_generic_to_shared(&buf[1][0]);
    const unsigned sbb[2] = {sb0, sb1};

    const __half* aeg = d_aeT_h + b * NU * NT;

    PC P;
    P.c0 = __float2half2_rn(0.992381f);
    P.c1 = __float2half2_rn(-0.282962f);
    P.c2 = __float2half2_rn(0.065192f);
    P.c3 = __float2half2_rn(-0.0087342f);
    P.c4 = __float2half2_rn(0.00059761f);
    P.c5 = __float2half2_rn(-1.6085e-5f);
    P.cl = __float2half2_rn(3.398f);

    stage_tile(sb0, aeg, tid);
    {
        const float* ap = d_ad + (b * NT + t0) * NU + tid;
        __half2 ad01 = __floats2half2_rn(ap[0],      ap[NU]);
        __half2 ad23 = __floats2half2_rn(ap[2 * NU], ap[3 * NU]);
        __half2 nu2  = __float2half2_rn(nu[tid]);
        uint4 p;
        p.x = *(unsigned*)&ad01;
        p.y = *(unsigned*)&ad23;
        p.z = *(unsigned*)&nu2;
        p.w = 0;
        pk[tid] = p;
    }

    float m0 = 0.f, m1 = 0.f, m2 = 0.f, m3 = 0.f;
    for (int t = 0; t < NTILES; ++t) {
        if (t < NTILES - 1)
            stage_tile(sbb[(t + 1) & 1], aeg + (t + 1) * TILE_HALFS, tid);
        if (t < NTILES - 1)
            asm volatile("cp.async.wait_group 1;" ::: "memory");
        else
            asm volatile("cp.async.wait_group 0;" ::: "memory");
        __syncthreads();

#pragma unroll
        for (int h = 0; h < 2; h++) {
            const __half* sa = &buf[t & 1][(h << 13) + tid];
            const int u0 = t * UT + h * 32;

            __half2 am01 = __float2half2_rn(0.f);
            __half2 am23 = __float2half2_rn(0.f);
            __half2 ap01 = __float2half2_rn(0.f);
            __half2 ap23 = __float2half2_rn(0.f);

#pragma unroll
            for (int i = 0; i < NM; i++) {
                {
                    __half  a  = sa[i << 8];
                    uint4   p  = pk[u0 + i];
                    __half2 ah = __half2half2(a);
                    __half2 c01 = __hadd2(ah, *(__half2*)&p.x);
                    __half2 c23 = __hadd2(ah, *(__half2*)&p.y);
                    unsigned t01, t23;
                    asm("tanh.approx.f16x2 %0, %1;" : "=r"(t01) : "r"(*(unsigned*)&c01));
                    asm("tanh.approx.f16x2 %0, %1;" : "=r"(t23) : "r"(*(unsigned*)&c23));
                    am01 = __hfma2(*(__half2*)&t01, *(__half2*)&p.z, am01);
                    am23 = __hfma2(*(__half2*)&t23, *(__half2*)&p.z, am23);
                }
                if (i < 32 - NM) {
                    int k = NM + i;
                    __half  a  = sa[k << 8];
                    uint4   p  = pk[u0 + k];
                    __half2 ah = __half2half2(a);
                    __half2 c01 = __hadd2(ah, *(__half2*)&p.x);
                    __half2 c23 = __hadd2(ah, *(__half2*)&p.y);
                    __half2 t01 = ptanh(c01, P);
                    __half2 t23 = ptanh(c23, P);
                    ap01 = __hfma2(t01, *(__half2*)&p.z, ap01);
                    ap23 = __hfma2(t23, *(__half2*)&p.z, ap23);
                }
            }
            float2 f01 = __half22float2(am01);
            float2 f23 = __half22float2(am23);
            float2 g01 = __half22float2(ap01);
            float2 g23 = __half22float2(ap23);
            m0 += f01.x + g01.x; m1 += f01.y + g01.y;
            m2 += f23.x + g23.x; m3 += f23.y + g23.y;
        }
        __syncthreads();
    }

    float4 mu = make_float4(m0, m1, m2, m3);
    float4 mx = mu;
#pragma unroll
    for (int o = 16; o; o >>= 1) {
        mx.x = fmaxf(mx.x, __shfl_xor_sync(0xffffffffu, mx.x, o));
        mx.y = fmaxf(mx.y, __shfl_xor_sync(0xffffffffu, mx.y, o));
        mx.z = fmaxf(mx.z, __shfl_xor_sync(0xffffffffu, mx.z, o));
        mx.w = fmaxf(mx.w, __shfl_xor_sync(0xffffffffu, mx.w, o));
    }
    if ((tid & 31) == 0) redM[wid] = mx;
    __syncthreads();
    mx = redM[0];
#pragma unroll
    for (int i = 1; i < 8; i++) {
        float4 r = redM[i];
        mx.x = fmaxf(mx.x, r.x); mx.y = fmaxf(mx.y, r.y);
        mx.z = fmaxf(mx.z, r.z); mx.w = fmaxf(mx.w, r.w);
    }
    float4 ex = make_float4(__expf(mu.x - mx.x), __expf(mu.y - mx.y),
                            __expf(mu.z - mx.z), __expf(mu.w - mx.w));
    float4 s = ex;
#pragma unroll
    for (int o = 16; o; o >>= 1) {
        s.x += __shfl_xor_sync(0xffffffffu, s.x, o);
        s.y += __shfl_xor_sync(0xffffffffu, s.y, o);
        s.z += __shfl_xor_sync(0xffffffffu, s.z, o);
        s.w += __shfl_xor_sync(0xffffffffu, s.w, o);
    }
    if ((tid & 31) == 0) redS[wid] = s;
    __syncthreads();
    s = redS[0];
#pragma unroll
    for (int i = 1; i < 8; i++) {
        float4 r = redS[i];
        s.x += r.x; s.y += r.y; s.z += r.z; s.w += r.w;
    }

    float* ap = d_alpha + (b * NT + t0) * NT + tid;
    ap[0]      = __fdividef(ex.x, s.x);
    ap[NT]     = __fdividef(ex.y, s.y);
    ap[2 * NT] = __fdividef(ex.z, s.z);
    ap[3 * NT] = __fdividef(ex.w, s.w);
}

extern "C" void kernel_launch(void* const* d_in, const int* in_sizes, int n_in,
                              void* d_out, int out_size)
{
    const float* en   = (const float*)d_in[0];
    const float* de   = (const float*)d_in[1];
    const float* w_en = (const float*)d_in[2];
    const float* w_de = (const float*)d_in[3];
    const float* nu   = (const float*)d_in[4];
    float* out = (float*)d_out;

    dim3 gg(4, 4, 16);               // 64x64 tiles -> 256 CTAs
    gemm_kernel<<<gg, 256>>>(en, de, w_en, w_de);
    attn_kernel<<<NB * (NT / 4), 256>>>(nu);
    dim3 gc(4, 4, 8);                // 128 CTAs
    ctx_kernel<<<gc, 256>>>(en, de, out);
}

// round 17
// speedup vs baseline: 1.1238x; 1.0435x over previous
#include <cuda_runtime.h>
#include <cuda_bf16.h>
#include <cuda_fp16.h>

#define NB 8
#define NT 256
#define ND 256
#define NU 256

__device__ __half d_aeT_h[NB * NU * NT];   // aeT[b][u][e] fp16
__device__ float  d_ad   [NB * NT * NU];   // ad [b][t][u] fp32
__device__ float  d_alpha[NB * NT * NT];   // alpha[b][t][e] fp32
__device__ __half d_w_h  [2 * 256 * 256];  // w_en, w_de as fp16

// ---------------------------------------------------------------------------
// fp16 MMA helper (m16n8k16, fp32 accumulate)
// ---------------------------------------------------------------------------
__device__ __forceinline__ void mma_f16(float c[4], unsigned a0, unsigned a1,
                                        unsigned a2, unsigned a3,
                                        unsigned b0, unsigned b1)
{
    asm volatile(
        "mma.sync.aligned.m16n8k16.row.col.f32.f16.f16.f32 "
        "{%0,%1,%2,%3}, {%4,%5,%6,%7}, {%8,%9}, {%0,%1,%2,%3};"
        : "+f"(c[0]), "+f"(c[1]), "+f"(c[2]), "+f"(c[3])
        : "r"(a0), "r"(a1), "r"(a2), "r"(a3), "r"(b0), "r"(b1));
}

__device__ __forceinline__ uint2 h4(float4 v)
{
    __half2 lo = __floats2half2_rn(v.x, v.y);
    __half2 hi = __floats2half2_rn(v.z, v.w);
    uint2 r;
    r.x = *(unsigned*)&lo;
    r.y = *(unsigned*)&hi;
    return r;
}

// ---------------------------------------------------------------------------
// Weight conversion: w_en, w_de fp32 -> d_w_h fp16 (runs once, ~1us)
// ---------------------------------------------------------------------------
__global__ __launch_bounds__(256) void wconv_kernel(const float* __restrict__ w_en,
                                                    const float* __restrict__ w_de)
{
    int i = blockIdx.x * 256 + threadIdx.x;          // 32768 float4s total
    const float* src = (i < 16384) ? w_en : w_de;
    int j = i & 16383;
    float4 v = ((const float4*)src)[j];
    ((uint2*)d_w_h)[i] = h4(v);
}

// ---------------------------------------------------------------------------
// fp16 GEMM body: CTA tile 64(M)x64(N), K-chunk 32 (2 x k16 MMA steps),
// 8 warps in 2(M)x4(N) grid, warp tile 32x16, accum c[2][2][4] fp32.
// SMEM: As[64][40] fp16 (20-bank rows: a-frag banks 20g+tig, conflict-free),
//       Bs[32][72] fp16 (b-frag half-pairs share a 4B word -> broadcast).
// A staged from fp32 gmem (convert at STS); B from fp16 gmem or fp32 (ctx).
// ---------------------------------------------------------------------------
#define GEMM_EPILOGUE_DECLS                                                    \
    const int tid  = threadIdx.x;                                             \
    const int w    = tid >> 5;                                                \
    const int lane = tid & 31;                                                \
    const int g    = lane >> 2;                                               \
    const int tig  = lane & 3;                                                \
    const int mw   = (w & 1) * 32;                                            \
    const int nw   = (w >> 1) * 16;

#define GEMM_COMPUTE_CHUNK                                                     \
    _Pragma("unroll")                                                          \
    for (int kt = 0; kt < 2; kt++) {                                           \
        unsigned a[2][4];                                                      \
        const int kk = kt * 16 + 2 * tig;                                      \
        _Pragma("unroll")                                                      \
        for (int mt = 0; mt < 2; mt++) {                                       \
            int r = mw + mt * 16 + g;                                          \
            a[mt][0] = *(const unsigned*)&As[r][kk];                           \
            a[mt][1] = *(const unsigned*)&As[r + 8][kk];                       \
            a[mt][2] = *(const unsigned*)&As[r][kk + 8];                       \
            a[mt][3] = *(const unsigned*)&As[r + 8][kk + 8];                   \
        }                                                                      \
        _Pragma("unroll")                                                      \
        for (int nt = 0; nt < 2; nt++) {                                       \
            int col = nw + nt * 8 + g;                                         \
            __half2 b0h = __halves2half2(Bs[kk][col], Bs[kk + 1][col]);        \
            __half2 b1h = __halves2half2(Bs[kk + 8][col], Bs[kk + 9][col]);    \
            unsigned b0 = *(unsigned*)&b0h;                                    \
            unsigned b1 = *(unsigned*)&b1h;                                    \
            mma_f16(c[0][nt], a[0][0], a[0][1], a[0][2], a[0][3], b0, b1);     \
            mma_f16(c[1][nt], a[1][0], a[1][1], a[1][2], a[1][3], b0, b1);     \
        }                                                                      \
    }

// ---------------------------------------------------------------------------
// Front GEMM: which=0 -> d_aeT_h[b][u][e] fp16 (transposed); which=1 -> d_ad.
// A = en/de (fp32 gmem), B = d_w_h (fp16 gmem). Grid (4,4,16) = 256 CTAs.
// ---------------------------------------------------------------------------
__global__ __launch_bounds__(256) void gemm_kernel(const float* __restrict__ en,
                                                   const float* __restrict__ de)
{
    const int z     = blockIdx.z;
    const int b     = z >> 1;
    const int which = z & 1;

    const float*  A  = which ? (de + b * NT * ND) : (en + b * NT * ND);
    const __half* Bm = d_w_h + which * 65536;

    const int m0 = blockIdx.y * 64;
    const int n0 = blockIdx.x * 64;

    __shared__ __half As[64][40];
    __shared__ __half Bs[32][72];

    GEMM_EPILOGUE_DECLS

    float c[2][2][4];
#pragma unroll
    for (int mt = 0; mt < 2; mt++)
#pragma unroll
        for (int nt = 0; nt < 2; nt++)
#pragma unroll
            for (int i = 0; i < 4; i++) c[mt][nt][i] = 0.f;

    // staging indices
    const int ar[2] = {tid >> 3, (tid + 256) >> 3};   // A rows (0..63)
    const int ac    = (tid & 7) << 2;                 // A k-offset (floats)
    const int bk    = tid >> 3;                       // B k-row (0..31)
    const int bn    = (tid & 7) << 3;                 // B n-offset (halves)

    float4 pa[2];
    uint4  pbh;
#pragma unroll
    for (int i = 0; i < 2; i++)
        pa[i] = *(const float4*)(A + (m0 + ar[i]) * 256 + 0 + ac);
    pbh = *(const uint4*)(Bm + (0 + bk) * 256 + n0 + bn);

    for (int t = 0; t < 8; ++t) {
        __syncthreads();
#pragma unroll
        for (int i = 0; i < 2; i++)
            *(uint2*)&As[ar[i]][ac] = h4(pa[i]);
        *(uint4*)&Bs[bk][bn] = pbh;
        __syncthreads();

        if (t < 7) {
            int k0 = (t + 1) * 32;
#pragma unroll
            for (int i = 0; i < 2; i++)
                pa[i] = *(const float4*)(A + (m0 + ar[i]) * 256 + k0 + ac);
            pbh = *(const uint4*)(Bm + (k0 + bk) * 256 + n0 + bn);
        }

        GEMM_COMPUTE_CHUNK
    }

    if (which == 0) {
        __half* dst = d_aeT_h + b * NU * NT;
#pragma unroll
        for (int mt = 0; mt < 2; mt++)
#pragma unroll
            for (int nt = 0; nt < 2; nt++) {
                int e0 = m0 + mw + mt * 16 + g;
                int u0 = n0 + nw + nt * 8 + 2 * tig;
                dst[u0 * NT + e0]           = __float2half(c[mt][nt][0]);
                dst[(u0 + 1) * NT + e0]     = __float2half(c[mt][nt][1]);
                dst[u0 * NT + e0 + 8]       = __float2half(c[mt][nt][2]);
                dst[(u0 + 1) * NT + e0 + 8] = __float2half(c[mt][nt][3]);
            }
    } else {
        float* dst = d_ad + b * NT * NU;
#pragma unroll
        for (int mt = 0; mt < 2; mt++)
#pragma unroll
            for (int nt = 0; nt < 2; nt++) {
                int row = m0 + mw + mt * 16 + g;
                int col = n0 + nw + nt * 8 + 2 * tig;
                *(float2*)(dst + row * NU + col)       = make_float2(c[mt][nt][0], c[mt][nt][1]);
                *(float2*)(dst + (row + 8) * NU + col) = make_float2(c[mt][nt][2], c[mt][nt][3]);
            }
    }
}

// ---------------------------------------------------------------------------
// Context GEMM: out = de + alpha @ en (both staged fp32 -> fp16 at STS).
// Grid (4,4,8) = 128 CTAs.
// ---------------------------------------------------------------------------
__global__ __launch_bounds__(256) void ctx_kernel(const float* __restrict__ en,
                                                  const float* __restrict__ de,
                                                  float* __restrict__ out)
{
    const int b = blockIdx.z;
    const float* A  = d_alpha + b * NT * NT;
    const float* Bm = en + b * NT * ND;

    const int m0 = blockIdx.y * 64;
    const int n0 = blockIdx.x * 64;

    __shared__ __half As[64][40];
    __shared__ __half Bs[32][72];

    GEMM_EPILOGUE_DECLS

    float c[2][2][4];
#pragma unroll
    for (int mt = 0; mt < 2; mt++)
#pragma unroll
        for (int nt = 0; nt < 2; nt++)
#pragma unroll
            for (int i = 0; i < 4; i++) c[mt][nt][i] = 0.f;

    const int ar[2] = {tid >> 3, (tid + 256) >> 3};
    const int ac    = (tid & 7) << 2;
    const int br[2] = {tid >> 4, (tid + 256) >> 4};   // B k-rows (0..31)
    const int bc    = (tid & 15) << 2;                // B n-offset (floats)

    float4 pa[2], pb[2];
#pragma unroll
    for (int i = 0; i < 2; i++)
        pa[i] = *(const float4*)(A + (m0 + ar[i]) * 256 + 0 + ac);
#pragma unroll
    for (int i = 0; i < 2; i++)
        pb[i] = *(const float4*)(Bm + (0 + br[i]) * 256 + n0 + bc);

    for (int t = 0; t < 8; ++t) {
        __syncthreads();
#pragma unroll
        for (int i = 0; i < 2; i++)
            *(uint2*)&As[ar[i]][ac] = h4(pa[i]);
#pragma unroll
        for (int i = 0; i < 2; i++)
            *(uint2*)&Bs[br[i]][bc] = h4(pb[i]);
        __syncthreads();

        if (t < 7) {
            int k0 = (t + 1) * 32;
#pragma unroll
            for (int i = 0; i < 2; i++)
                pa[i] = *(const float4*)(A + (m0 + ar[i]) * 256 + k0 + ac);
#pragma unroll
            for (int i = 0; i < 2; i++)
                pb[i] = *(const float4*)(Bm + (k0 + br[i]) * 256 + n0 + bc);
        }

        GEMM_COMPUTE_CHUNK
    }

    const float* deb = de + b * NT * ND;
    float* ob = out + b * NT * ND;
#pragma unroll
    for (int mt = 0; mt < 2; mt++)
#pragma unroll
        for (int nt = 0; nt < 2; nt++) {
            int row = m0 + mw + mt * 16 + g;
            int col = n0 + nw + nt * 8 + 2 * tig;
            float2 d0 = *(const float2*)(deb + row * ND + col);
            float2 d1 = *(const float2*)(deb + (row + 8) * ND + col);
            *(float2*)(ob + row * ND + col) =
                make_float2(c[mt][nt][0] + d0.x, c[mt][nt][1] + d0.y);
            *(float2*)(ob + (row + 8) * ND + col) =
                make_float2(c[mt][nt][2] + d1.x, c[mt][nt][3] + d1.y);
        }
}

// ---------------------------------------------------------------------------
// Attn kernel (unchanged from R16): scores (19 MUFU + 13 poly per 32 u,
// UT=64 staged tiles) + batched softmax -> alpha fp32.
// ---------------------------------------------------------------------------
#define UT 64
#define TILE_HALFS (UT * 256)
#define NTILES (256 / UT)
#define NM 19

__device__ __forceinline__ void stage_tile(unsigned sbase, const __half* g, int tid)
{
    unsigned s = sbase + tid * 16;
    const char* gp = (const char*)g + tid * 16;
#pragma unroll
    for (int i = 0; i < 8; i++)
        asm volatile("cp.async.cg.shared.global [%0], [%1], 16;\n"
                     :: "r"(s + i * 4096), "l"(gp + i * 4096) : "memory");
    asm volatile("cp.async.commit_group;" ::: "memory");
}

struct PC { __half2 c0, c1, c2, c3, c4, c5, cl; };

__device__ __forceinline__ __half2 ptanh(__half2 x, const PC& P)
{
    __half2 xc = __hmax2(__hmin2(x, P.cl), __hneg2(P.cl));
    __half2 z  = __hmul2(xc, xc);
    __half2 h  = __hfma2(P.c5, z, P.c4);
    h = __hfma2(h, z, P.c3);
    h = __hfma2(h, z, P.c2);
    h = __hfma2(h, z, P.c1);
    h = __hfma2(h, z, P.c0);
    return __hmul2(xc, h);
}

__global__ __launch_bounds__(256) void attn_kernel(const float* __restrict__ nu)
{
    const int b   = blockIdx.x >> 6;
    const int t0  = (blockIdx.x & 63) << 2;
    const int tid = threadIdx.x;
    const int wid = tid >> 5;

    __shared__ __half buf[2][TILE_HALFS];   // 64KB double buffer
    __shared__ uint4  pk[256];
    __shared__ float4 redM[8];
    __shared__ float4 redS[8];

    const unsigned sb0 = (unsigned)__cvta_generic_to_shared(&buf[0][0]);
    const unsigned sb1 = (unsigned)__cvta_generic_to_shared(&buf[1][0]);
    const unsigned sbb[2] = {sb0, sb1};

    const __half* aeg = d_aeT_h + b * NU * NT;

    PC P;
    P.c0 = __float2half2_rn(0.992381f);
    P.c1 = __float2half2_rn(-0.282962f);
    P.c2 = __float2half2_rn(0.065192f);
    P.c3 = __float2half2_rn(-0.0087342f);
    P.c4 = __float2half2_rn(0.00059761f);
    P.c5 = __float2half2_rn(-1.6085e-5f);
    P.cl = __float2half2_rn(3.398f);

    stage_tile(sb0, aeg, tid);
    {
        const float* ap = d_ad + (b * NT + t0) * NU + tid;
        __half2 ad01 = __floats2half2_rn(ap[0],      ap[NU]);
        __half2 ad23 = __floats2half2_rn(ap[2 * NU], ap[3 * NU]);
        __half2 nu2  = __float2half2_rn(nu[tid]);
        uint4 p;
        p.x = *(unsigned*)&ad01;
        p.y = *(unsigned*)&ad23;
        p.z = *(unsigned*)&nu2;
        p.w = 0;
        pk[tid] = p;
    }

    float m0 = 0.f, m1 = 0.f, m2 = 0.f, m3 = 0.f;
    for (int t = 0; t < NTILES; ++t) {
        if (t < NTILES - 1)
            stage_tile(sbb[(t + 1) & 1], aeg + (t + 1) * TILE_HALFS, tid);
        if (t < NTILES - 1)
            asm volatile("cp.async.wait_group 1;" ::: "memory");
        else
            asm volatile("cp.async.wait_group 0;" ::: "memory");
        __syncthreads();

#pragma unroll
        for (int h = 0; h < 2; h++) {
            const __half* sa = &buf[t & 1][(h << 13) + tid];
            const int u0 = t * UT + h * 32;

            __half2 am01 = __float2half2_rn(0.f);
            __half2 am23 = __float2half2_rn(0.f);
            __half2 ap01 = __float2half2_rn(0.f);
            __half2 ap23 = __float2half2_rn(0.f);

#pragma unroll
            for (int i = 0; i < NM; i++) {
                {
                    __half  a  = sa[i << 8];
                    uint4   p  = pk[u0 + i];
                    __half2 ah = __half2half2(a);
                    __half2 c01 = __hadd2(ah, *(__half2*)&p.x);
                    __half2 c23 = __hadd2(ah, *(__half2*)&p.y);
                    unsigned t01, t23;
                    asm("tanh.approx.f16x2 %0, %1;" : "=r"(t01) : "r"(*(unsigned*)&c01));
                    asm("tanh.approx.f16x2 %0, %1;" : "=r"(t23) : "r"(*(unsigned*)&c23));
                    am01 = __hfma2(*(__half2*)&t01, *(__half2*)&p.z, am01);
                    am23 = __hfma2(*(__half2*)&t23, *(__half2*)&p.z, am23);
                }
                if (i < 32 - NM) {
                    int k = NM + i;
                    __half  a  = sa[k << 8];
                    uint4   p  = pk[u0 + k];
                    __half2 ah = __half2half2(a);
                    __half2 c01 = __hadd2(ah, *(__half2*)&p.x);
                    __half2 c23 = __hadd2(ah, *(__half2*)&p.y);
                    __half2 t01 = ptanh(c01, P);
                    __half2 t23 = ptanh(c23, P);
                    ap01 = __hfma2(t01, *(__half2*)&p.z, ap01);
                    ap23 = __hfma2(t23, *(__half2*)&p.z, ap23);
                }
            }
            float2 f01 = __half22float2(am01);
            float2 f23 = __half22float2(am23);
            float2 g01 = __half22float2(ap01);
            float2 g23 = __half22float2(ap23);
            m0 += f01.x + g01.x; m1 += f01.y + g01.y;
            m2 += f23.x + g23.x; m3 += f23.y + g23.y;
        }
        __syncthreads();
    }

    float4 mu = make_float4(m0, m1, m2, m3);
    float4 mx = mu;
#pragma unroll
    for (int o = 16; o; o >>= 1) {
        mx.x = fmaxf(mx.x, __shfl_xor_sync(0xffffffffu, mx.x, o));
        mx.y = fmaxf(mx.y, __shfl_xor_sync(0xffffffffu, mx.y, o));
        mx.z = fmaxf(mx.z, __shfl_xor_sync(0xffffffffu, mx.z, o));
        mx.w = fmaxf(mx.w, __shfl_xor_sync(0xffffffffu, mx.w, o));
    }
    if ((tid & 31) == 0) redM[wid] = mx;
    __syncthreads();
    mx = redM[0];
#pragma unroll
    for (int i = 1; i < 8; i++) {
        float4 r = redM[i];
        mx.x = fmaxf(mx.x, r.x); mx.y = fmaxf(mx.y, r.y);
        mx.z = fmaxf(mx.z, r.z); mx.w = fmaxf(mx.w, r.w);
    }
    float4 ex = make_float4(__expf(mu.x - mx.x), __expf(mu.y - mx.y),
                            __expf(mu.z - mx.z), __expf(mu.w - mx.w));
    float4 s = ex;
#pragma unroll
    for (int o = 16; o; o >>= 1) {
        s.x += __shfl_xor_sync(0xffffffffu, s.x, o);
        s.y += __shfl_xor_sync(0xffffffffu, s.y, o);
        s.z += __shfl_xor_sync(0xffffffffu, s.z, o);
        s.w += __shfl_xor_sync(0xffffffffu, s.w, o);
    }
    if ((tid & 31) == 0) redS[wid] = s;
    __syncthreads();
    s = redS[0];
#pragma unroll
    for (int i = 1; i < 8; i++) {
        float4 r = redS[i];
        s.x += r.x; s.y += r.y; s.z += r.z; s.w += r.w;
    }

    float* ap = d_alpha + (b * NT + t0) * NT + tid;
    ap[0]      = __fdividef(ex.x, s.x);
    ap[NT]     = __fdividef(ex.y, s.y);
    ap[2 * NT] = __fdividef(ex.z, s.z);
    ap[3 * NT] = __fdividef(ex.w, s.w);
}

extern "C" void kernel_launch(void* const* d_in, const int* in_sizes, int n_in,
                              void* d_out, int out_size)
{
    const float* en   = (const float*)d_in[0];
    const float* de   = (const float*)d_in[1];
    const float* w_en = (const float*)d_in[2];
    const float* w_de = (const float*)d_in[3];
    const float* nu   = (const float*)d_in[4];
    float* out = (float*)d_out;

    wconv_kernel<<<128, 256>>>(w_en, w_de);
    dim3 gg(4, 4, 16);               // 64x64 tiles -> 256 CTAs
    gemm_kernel<<<gg, 256>>>(en, de);
    attn_kernel<<<NB * (NT / 4), 256>>>(nu);
    dim3 gc(4, 4, 8);                // 128 CTAs
    ctx_kernel<<<gc, 256>>>(en, de, out);
}